// round 14
// baseline (speedup 1.0000x reference)
#include <cuda_runtime.h>
#include <cuda_bf16.h>
#include <cstdint>

#define Bn   512
#define Tn   64
#define Mn   256
#define Pn   256
#define G4n  1024
#define NC   296            // persistent grid: 2 CTAs per SM, all co-resident

// ---------------- device-global scratch (allocation-free) -------------------
__device__ __align__(256) float g_y1 [Bn * Tn * Mn]; // enc @ Ud^T, fp32 (33.5 MB)
__device__ __align__(256) float g_hs [Bn * 2 * Pn];  // [h | s], lda=512 (fp32 truth)
__device__ __align__(256) float g_ct [Bn * Mn];
__device__ __align__(256) float g_x1p0[Bn * Mn];     // split-K partials of x1
__device__ __align__(256) float g_x1p1[Bn * Mn];
__device__ __align__(256) float g_ghp0[Bn * G4n];    // split-K partials of gh
__device__ __align__(256) float g_ghp1[Bn * G4n];
__device__ __align__(256) float g_u  [2 * Pn + 1];

// per-row-block producer/consumer flags (8 blocks of 64 batch rows)
__device__ int g_x1d[8];    // x1 tasks done (8 per block per step)
__device__ int g_ghd[8];    // gh tasks done (32 per block per step)
__device__ int g_att[8];    // attn CTA arrivals (32 per block per step)

// bf16 hi/lo split operands for tensor-core GEMMs
__device__ __align__(256) __nv_bfloat16 g_hs_hi [Bn * 2 * Pn];
__device__ __align__(256) __nv_bfloat16 g_hs_lo [Bn * 2 * Pn];
__device__ __align__(256) __nv_bfloat16 g_Wd_hi [Mn * 2 * Pn];
__device__ __align__(256) __nv_bfloat16 g_Wd_lo [Mn * 2 * Pn];
__device__ __align__(256) __nv_bfloat16 g_Whh_hi[G4n * Pn];
__device__ __align__(256) __nv_bfloat16 g_Whh_lo[G4n * Pn];
__device__ __align__(256) __nv_bfloat16 g_Ud_hi [Mn * Mn];
__device__ __align__(256) __nv_bfloat16 g_Ud_lo [Mn * Mn];
__device__ __align__(256) __nv_bfloat16 g_enc_hi[Bn * Tn * Mn];
__device__ __align__(256) __nv_bfloat16 g_enc_lo[Bn * Tn * Mn];

// ---------------- math helpers ---------------------------------------------
__device__ __forceinline__ float tanh_acc(float x) {        // accurate (LSTM)
    float e = __expf(2.0f * x);
    return 1.0f - __fdividef(2.0f, e + 1.0f);
}
__device__ __forceinline__ float tanh_fast(float x) {       // MUFU.TANH (attn)
    float r;
    asm("tanh.approx.f32 %0, %1;" : "=f"(r) : "f"(x));
    return r;
}
__device__ __forceinline__ float sigm(float x) {
    return __fdividef(1.0f, 1.0f + __expf(-x));
}
__device__ __forceinline__ float block_reduce_256(float v, float* red8) {
    #pragma unroll
    for (int o = 16; o > 0; o >>= 1) v += __shfl_xor_sync(0xffffffffu, v, o);
    int w = threadIdx.x >> 5, l = threadIdx.x & 31;
    __syncthreads();
    if (l == 0) red8[w] = v;
    __syncthreads();
    float r = red8[0];
    #pragma unroll
    for (int i = 1; i < 8; i++) r += red8[i];
    return r;
}
__device__ __forceinline__ void split_store(float v, __nv_bfloat16* hi,
                                            __nv_bfloat16* lo) {
    __nv_bfloat16 h = __float2bfloat16(v);
    *hi = h;
    *lo = __float2bfloat16(v - __bfloat162float(h));
}
__device__ __forceinline__ void split_store2(float vx, float vy,
                                             __nv_bfloat16* hi, __nv_bfloat16* lo) {
    __nv_bfloat16 hx = __float2bfloat16(vx), hy = __float2bfloat16(vy);
    __nv_bfloat162 h2; h2.x = hx; h2.y = hy;
    *(__nv_bfloat162*)hi = h2;
    __nv_bfloat162 l2;
    l2.x = __float2bfloat16(vx - __bfloat162float(hx));
    l2.y = __float2bfloat16(vy - __bfloat162float(hy));
    *(__nv_bfloat162*)lo = l2;
}

// ---------------- flag sync primitives --------------------------------------
__device__ __forceinline__ void wait_flag(const int* p, int target) {
    if (threadIdx.x == 0) {
        while (*(volatile const int*)p < target) __nanosleep(20);
    }
    __syncthreads();
}
__device__ __forceinline__ void flag_add(int* p) {
    __threadfence();            // per-thread release of prior stores
    __syncthreads();
    if (threadIdx.x == 0) atomicAdd(p, 1);
}

// ---------------- mma / ldmatrix / cp.async primitives ----------------------
__device__ __forceinline__ void ldm4(uint32_t* r, uint32_t addr) {
    asm volatile("ldmatrix.sync.aligned.m8n8.x4.shared.b16 {%0,%1,%2,%3}, [%4];"
        : "=r"(r[0]), "=r"(r[1]), "=r"(r[2]), "=r"(r[3]) : "r"(addr));
}
__device__ __forceinline__ void mma_bf16(float* d, const uint32_t* a,
                                         uint32_t b0, uint32_t b1) {
    asm volatile(
        "mma.sync.aligned.m16n8k16.row.col.f32.bf16.bf16.f32 "
        "{%0,%1,%2,%3}, {%4,%5,%6,%7}, {%8,%9}, {%0,%1,%2,%3};"
        : "+f"(d[0]), "+f"(d[1]), "+f"(d[2]), "+f"(d[3])
        : "r"(a[0]), "r"(a[1]), "r"(a[2]), "r"(a[3]), "r"(b0), "r"(b1));
}
template<bool CG>
__device__ __forceinline__ void cpa16(uint32_t dst, const void* src) {
    if (CG)
        asm volatile("cp.async.cg.shared.global [%0], [%1], 16;\n"
                     :: "r"(dst), "l"(src));
    else
        asm volatile("cp.async.ca.shared.global [%0], [%1], 16;\n"
                     :: "r"(dst), "l"(src));
}
__device__ __forceinline__ void cpa_commit() {
    asm volatile("cp.async.commit_group;\n");
}

// ---------------- conversions (init merged) ----------------------------------
__global__ void conv_enc_kernel(const float* __restrict__ enc) {
    size_t i = ((size_t)blockIdx.x * 256 + threadIdx.x) * 4;
    float4 v = *(const float4*)&enc[i];
    __nv_bfloat16 h[4], l[4];
    float vv[4] = {v.x, v.y, v.z, v.w};
    #pragma unroll
    for (int q = 0; q < 4; q++) {
        h[q] = __float2bfloat16(vv[q]);
        l[q] = __float2bfloat16(vv[q] - __bfloat162float(h[q]));
    }
    __nv_bfloat162 ph0, ph1, pl0, pl1;
    ph0.x = h[0]; ph0.y = h[1]; ph1.x = h[2]; ph1.y = h[3];
    pl0.x = l[0]; pl0.y = l[1]; pl1.x = l[2]; pl1.y = l[3];
    *(__nv_bfloat162*)&g_enc_hi[i]     = ph0;
    *(__nv_bfloat162*)&g_enc_hi[i + 2] = ph1;
    *(__nv_bfloat162*)&g_enc_lo[i]     = pl0;
    *(__nv_bfloat162*)&g_enc_lo[i + 2] = pl1;
}
__global__ void conv_weights_kernel(const float* __restrict__ Wd,
                                    const float* __restrict__ Whh,
                                    const float* __restrict__ Ud) {
    int i = blockIdx.x * 256 + threadIdx.x;
    if (i < Mn * 2 * Pn) split_store(Wd[i], &g_Wd_hi[i], &g_Wd_lo[i]);
    if (i < G4n * Pn)    split_store(Whh[i], &g_Whh_hi[i], &g_Whh_lo[i]);
    if (i < Mn * Mn)     split_store(Ud[i],  &g_Ud_hi[i],  &g_Ud_lo[i]);
    if (i < Bn * 2 * Pn) {                    // merged state init
        g_hs[i] = 0.0f;
        g_hs_hi[i] = __float2bfloat16(0.0f);
        g_hs_lo[i] = __float2bfloat16(0.0f);
    }
    if (i < 8) { g_x1d[i] = 0; g_ghd[i] = 0; g_att[i] = 0; }
}

// ---------------- fold head (parallel): u = vy_w @ Wy_w ----------------------
__global__ void __launch_bounds__(256) compute_u_kernel(
        const float* __restrict__ vy_w, const float* __restrict__ Wy_w,
        const float* __restrict__ Wy_b, const float* __restrict__ vy_b) {
    const int w = threadIdx.x >> 5, l = threadIdx.x & 31;
    const int j = blockIdx.x * 8 + w;
    float s = 0.0f;
    #pragma unroll
    for (int n = l; n < Pn; n += 32) s += vy_w[n] * Wy_w[n * 512 + j];
    #pragma unroll
    for (int o = 16; o > 0; o >>= 1) s += __shfl_xor_sync(0xffffffffu, s, o);
    if (l == 0) g_u[j] = s;

    if (blockIdx.x == 0 && w == 0) {
        float v = 0.0f;
        #pragma unroll
        for (int n = l; n < Pn; n += 32) v += vy_w[n] * Wy_b[n];
        #pragma unroll
        for (int o = 16; o > 0; o >>= 1) v += __shfl_xor_sync(0xffffffffu, v, o);
        if (l == 0) g_u[2 * Pn] = v + vy_b[0];
    }
}

// ---------------- split-bf16 MMA 64x64 tile, cp.async double-buffered -------
#define ST    40
#define PLB   (64 * ST * 2)          // bytes per plane  (5120)
#define BUFB  (4 * PLB)              // bytes per buffer (20480)

template<bool ACG>
__device__ __forceinline__ void mma_tile64(
    const __nv_bfloat16* __restrict__ Ah, const __nv_bfloat16* __restrict__ Al,
    int lda,
    const __nv_bfloat16* __restrict__ Bh, const __nv_bfloat16* __restrict__ Bl,
    int ldb,
    float* __restrict__ C, int ldc, int r0, int c0, int k0, int K,
    const float* __restrict__ b1, const float* __restrict__ b2)
{
    __shared__ __align__(16) __nv_bfloat16 sm[2 * 4 * 64 * ST];
    const int tid = threadIdx.x;
    const int wid = tid >> 5, lane = tid & 31;
    const int wr = wid & 3, wc = wid >> 2;
    const uint32_t sb = (uint32_t)__cvta_generic_to_shared(sm);

    const int row = tid >> 2, ko = (tid & 3) * 8;
    const __nv_bfloat16* pAh = Ah + (size_t)(r0 + row) * lda + k0 + ko;
    const __nv_bfloat16* pAl = Al + (size_t)(r0 + row) * lda + k0 + ko;
    const __nv_bfloat16* pBh = Bh + (size_t)(c0 + row) * ldb + k0 + ko;
    const __nv_bfloat16* pBl = Bl + (size_t)(c0 + row) * ldb + k0 + ko;
    const uint32_t dA = sb + (uint32_t)(row * ST + ko) * 2;

    float acc[4][4];
    #pragma unroll
    for (int n = 0; n < 4; n++)
        #pragma unroll
        for (int i = 0; i < 4; i++) acc[n][i] = 0.0f;

    const int grp = lane >> 3, lr = lane & 7;
    const uint32_t aAddr = sb +
        (uint32_t)((wr * 16 + ((grp & 1) << 3) + lr) * ST + ((grp >> 1) << 3)) * 2;
    const uint32_t bAddr = sb + 2 * PLB +
        (uint32_t)((wc * 32 + ((grp >> 1) << 3) + lr) * ST + ((grp & 1) << 3)) * 2;

    const int nch = K >> 5;
    {
        cpa16<ACG>(dA,            pAh);
        cpa16<ACG>(dA + PLB,      pAl);
        cpa16<false>(dA + 2 * PLB,  pBh);
        cpa16<false>(dA + 3 * PLB,  pBl);
        cpa_commit();
    }
    for (int c = 0; c < nch; c++) {
        if (c + 1 < nch) {
            const int kb = (c + 1) * 32;
            const uint32_t d = dA + ((c + 1) & 1) * BUFB;
            cpa16<ACG>(d,           pAh + kb);
            cpa16<ACG>(d + PLB,     pAl + kb);
            cpa16<false>(d + 2 * PLB, pBh + kb);
            cpa16<false>(d + 3 * PLB, pBl + kb);
            cpa_commit();
            asm volatile("cp.async.wait_group 1;\n");
        } else {
            asm volatile("cp.async.wait_group 0;\n");
        }
        __syncthreads();
        const uint32_t bo = (c & 1) * BUFB;
        #pragma unroll
        for (int kk = 0; kk < 32; kk += 16) {
            uint32_t ah[4], al[4], bh[2][4], bl[2][4];
            ldm4(ah,   aAddr + bo + kk * 2);
            ldm4(al,   aAddr + bo + PLB + kk * 2);
            ldm4(bh[0], bAddr + bo + kk * 2);
            ldm4(bh[1], bAddr + bo + 16 * ST * 2 + kk * 2);
            ldm4(bl[0], bAddr + bo + PLB + kk * 2);
            ldm4(bl[1], bAddr + bo + PLB + 16 * ST * 2 + kk * 2);
            #pragma unroll
            for (int nt = 0; nt < 4; nt++) {
                const int p = nt >> 1, q = (nt & 1) * 2;
                mma_bf16(acc[nt], ah, bh[p][q], bh[p][q + 1]);   // hi*hi
                mma_bf16(acc[nt], ah, bl[p][q], bl[p][q + 1]);   // hi*lo
                mma_bf16(acc[nt], al, bh[p][q], bh[p][q + 1]);   // lo*hi
            }
        }
        __syncthreads();
    }

    const int rl = lane >> 2, cl = (lane & 3) * 2;
    const int gr = r0 + wr * 16 + rl;
    #pragma unroll
    for (int nt = 0; nt < 4; nt++) {
        const int gc = c0 + wc * 32 + nt * 8 + cl;
        float v0 = 0.0f, v1 = 0.0f;
        if (b1) { v0 += b1[gc]; v1 += b1[gc + 1]; }
        if (b2) { v0 += b2[gc]; v1 += b2[gc + 1]; }
        C[(size_t)gr * ldc + gc]           = acc[nt][0] + v0;
        C[(size_t)gr * ldc + gc + 1]       = acc[nt][1] + v1;
        C[(size_t)(gr + 8) * ldc + gc]     = acc[nt][2] + v0;
        C[(size_t)(gr + 8) * ldc + gc + 1] = acc[nt][3] + v1;
    }
}

// y1 = enc(32768x256) @ Ud^T(256x256), fp32 out, 3-plane accurate
__global__ void __launch_bounds__(256) y1_mma_kernel() {
    mma_tile64<false>(g_enc_hi, g_enc_lo, Mn, g_Ud_hi, g_Ud_lo, Mn,
                      g_y1, Mn, blockIdx.x * 64, blockIdx.y * 64, 0, Mn,
                      nullptr, nullptr);
}

// gh-only GEMM for the 2 extra steps (split-K x2; grid (8,32))
__global__ void __launch_bounds__(256) step_gemm_gh(
        const float* __restrict__ bih, const float* __restrict__ bhh) {
    const int r0 = blockIdx.x * 64;
    const int kh = blockIdx.y & 1, ct = blockIdx.y >> 1;
    mma_tile64<false>(g_hs_hi, g_hs_lo, 512, g_Whh_hi, g_Whh_lo, 256,
                      kh ? g_ghp1 : g_ghp0, G4n, r0, ct * 64, kh * 128, 128,
                      kh ? nullptr : bih, kh ? nullptr : bhh);
}

// ---------------- attention + LSTM: one row per 128-thread half --------------
__device__ __forceinline__ void attn_half(
        int b, int t_step, int htid,
        const float* __restrict__ enc, const float* __restrict__ y,
        const float* __restrict__ wt_w, const float* __restrict__ wt_b,
        const float* __restrict__ Wih,
        float* x1s, const float* pv, float* ls, float* red4, float* ytilp,
        const int* ghflag, int ghtarget) {
    const int w = htid >> 5, l = htid & 31;     // warp 0..3 within half
    const int m0 = 2 * htid;                    // contiguous column pair

    {
        float2 xa = __ldcg((const float2*)&g_x1p0[b * Mn + m0]);
        float2 xb = __ldcg((const float2*)&g_x1p1[b * Mn + m0]);
        x1s[m0]     = xa.x + xb.x;
        x1s[m0 + 1] = xa.y + xb.y;
    }
    __syncthreads();

    // register-cache x1 for this lane's 4 pairs
    float px[8];
    #pragma unroll
    for (int j = 0; j < 4; j++) {
        int p = l + 32 * j;
        float2 xv = *(const float2*)&x1s[2 * p];
        px[2 * j]     = xv.x;
        px[2 * j + 1] = xv.y;
    }

    // logits: warp w -> 16 t; coalesced fp32 float2 y1 loads
    const float2* yrow0 = (const float2*)&g_y1[((size_t)b * Tn + w * 16) * Mn];
    #pragma unroll
    for (int idx = 0; idx < 16; idx++) {
        const float2* yrow = yrow0 + idx * (Mn / 2);
        float sum = 0.0f;
        #pragma unroll
        for (int j = 0; j < 4; j++) {
            int p = l + 32 * j;
            float2 yv = yrow[p];
            sum += tanh_fast(px[2 * j]     + yv.x) * pv[2 * j];
            sum += tanh_fast(px[2 * j + 1] + yv.y) * pv[2 * j + 1];
        }
        #pragma unroll
        for (int o = 16; o > 0; o >>= 1) sum += __shfl_xor_sync(0xffffffffu, sum, o);
        if (l == 0) ls[w * 16 + idx] = sum;
    }
    __syncthreads();

    if (w == 0) {                          // softmax over T=64 (warp 0 of half)
        float a = ls[l], c = ls[l + 32];
        float mx = fmaxf(a, c);
        #pragma unroll
        for (int o = 16; o > 0; o >>= 1) mx = fmaxf(mx, __shfl_xor_sync(0xffffffffu, mx, o));
        float e0 = __expf(a - mx), e1 = __expf(c - mx);
        float ts = e0 + e1;
        #pragma unroll
        for (int o = 16; o > 0; o >>= 1) ts += __shfl_xor_sync(0xffffffffu, ts, o);
        float inv = __fdividef(1.0f, ts);
        ls[l]      = e0 * inv;
        ls[l + 32] = e1 * inv;
    }
    __syncthreads();

    // context: fp32 enc, contiguous float2 per thread (accuracy-critical)
    float a0 = 0.0f, a1 = 0.0f;
    const float* encb = &enc[(size_t)b * Tn * Mn];
    #pragma unroll 8
    for (int t = 0; t < Tn; t++) {
        float beta = ls[t];
        float2 ev = *(const float2*)&encb[t * Mn + m0];
        a0 += beta * ev.x;
        a1 += beta * ev.y;
    }
    *(float2*)&g_ct[b * Mn + m0] = make_float2(a0, a1);

    // y_til reduce over 256 (2 per thread, 4 warps)
    {
        float2 wv = *(const float2*)&wt_w[m0];
        float v = a0 * wv.x + a1 * wv.y;
        #pragma unroll
        for (int o = 16; o > 0; o >>= 1) v += __shfl_xor_sync(0xffffffffu, v, o);
        if (l == 0) red4[w] = v;
    }
    __syncthreads();
    if (htid == 0)
        *ytilp = red4[0] + red4[1] + red4[2] + red4[3]
               + y[b * Tn + t_step] * wt_w[Mn] + wt_b[0];
    __syncthreads();
    const float ytil = *ytilp;

    // wait for this row-block's gh tasks (overlapped with phases above)
    if (threadIdx.x == 0) {
        while (*(volatile const int*)ghflag < ghtarget) __nanosleep(20);
    }
    __syncthreads();

    // LSTM cell for the column pair (i,f,g,o; biases folded into ghp0)
    const float* gh0 = &g_ghp0[(size_t)b * G4n];
    const float* gh1 = &g_ghp1[(size_t)b * G4n];
    float2 ig, fg, gg, og;
    {
        float2 a = __ldcg((const float2*)(gh0 + m0));
        float2 c = __ldcg((const float2*)(gh1 + m0));
        float2 wv = *(const float2*)(Wih + m0);
        ig = make_float2(a.x + c.x + ytil * wv.x, a.y + c.y + ytil * wv.y);
    }
    {
        float2 a = __ldcg((const float2*)(gh0 + Pn + m0));
        float2 c = __ldcg((const float2*)(gh1 + Pn + m0));
        float2 wv = *(const float2*)(Wih + Pn + m0);
        fg = make_float2(a.x + c.x + ytil * wv.x, a.y + c.y + ytil * wv.y);
    }
    {
        float2 a = __ldcg((const float2*)(gh0 + 2 * Pn + m0));
        float2 c = __ldcg((const float2*)(gh1 + 2 * Pn + m0));
        float2 wv = *(const float2*)(Wih + 2 * Pn + m0);
        gg = make_float2(a.x + c.x + ytil * wv.x, a.y + c.y + ytil * wv.y);
    }
    {
        float2 a = __ldcg((const float2*)(gh0 + 3 * Pn + m0));
        float2 c = __ldcg((const float2*)(gh1 + 3 * Pn + m0));
        float2 wv = *(const float2*)(Wih + 3 * Pn + m0);
        og = make_float2(a.x + c.x + ytil * wv.x, a.y + c.y + ytil * wv.y);
    }
    float2 so = *(const float2*)&g_hs[b * 512 + 256 + m0];  // CTA-local state
    float cnx = sigm(fg.x) * so.x + sigm(ig.x) * tanh_acc(gg.x);
    float cny = sigm(fg.y) * so.y + sigm(ig.y) * tanh_acc(gg.y);
    float hnx = sigm(og.x) * tanh_acc(cnx);
    float hny = sigm(og.y) * tanh_acc(cny);
    *(float2*)&g_hs[b * 512 + 256 + m0] = make_float2(cnx, cny);
    *(float2*)&g_hs[b * 512 + m0]       = make_float2(hnx, hny);
    split_store2(hnx, hny, &g_hs_hi[b * 512 + m0],       &g_hs_lo[b * 512 + m0]);
    split_store2(cnx, cny, &g_hs_hi[b * 512 + 256 + m0], &g_hs_lo[b * 512 + 256 + m0]);
}

// ---------------- persistent 64-step loop, flag-pipelined --------------------
// Task decode (id&7 = row-block, spreads each block's tasks across CTAs):
//   x1: id = pc (0..63):    r=id&7, kh=(id>>3)&1, c=id>>4 (0..3)
//   gh: id (0..255):        r=id&7, kh=(id>>3)&1, c=id>>4 (0..15)
//       first task id=pc-64; CTAs 64..87 also take id=232+(pc-64)
__global__ void __launch_bounds__(256, 2) persist_kernel(
        const float* __restrict__ enc, const float* __restrict__ y,
        const float* __restrict__ vd_w, const float* __restrict__ wt_w,
        const float* __restrict__ wt_b, const float* __restrict__ Wih,
        const float* __restrict__ Wd_b, const float* __restrict__ bih,
        const float* __restrict__ bhh) {
    __shared__ float s_x1[2][Mn], s_v[Mn], s_ls[2][Tn], s_red[2][4], s_yt[2];
    s_v[threadIdx.x] = vd_w[threadIdx.x];    // loop-invariant
    __syncthreads();

    const int pc   = blockIdx.x;
    const int half = threadIdx.x >> 7;       // 0 or 1
    const int htid = threadIdx.x & 127;

    // register-cache v for this lane's 4 pairs (same mapping as px)
    float pv[8];
    {
        const int l = htid & 31;
        #pragma unroll
        for (int j = 0; j < 4; j++) {
            int p = l + 32 * j;
            float2 vv = *(const float2*)&s_v[2 * p];
            pv[2 * j]     = vv.x;
            pv[2 * j + 1] = vv.y;
        }
    }

    for (int t = 0; t < Tn; t++) {
        if (pc < 64) {
            const int r = pc & 7, kh = (pc >> 3) & 1, c = pc >> 4;
            if (t) wait_flag(&g_att[r], 32 * t);
            mma_tile64<true>(g_hs_hi, g_hs_lo, 512, g_Wd_hi, g_Wd_lo, 512,
                             kh ? g_x1p1 : g_x1p0, Mn, r * 64, c * 64,
                             kh * 256, 256, kh ? nullptr : Wd_b, nullptr);
            flag_add(&g_x1d[r]);
        } else {
            int id = pc - 64;
            {
                const int r = id & 7, kh = (id >> 3) & 1, c = id >> 4;
                if (t) wait_flag(&g_att[r], 32 * t);
                mma_tile64<true>(g_hs_hi, g_hs_lo, 512, g_Whh_hi, g_Whh_lo, 256,
                                 kh ? g_ghp1 : g_ghp0, G4n, r * 64, c * 64,
                                 kh * 128, 128,
                                 kh ? nullptr : bih, kh ? nullptr : bhh);
                flag_add(&g_ghd[r]);
            }
            if (pc < 88) {
                id = 232 + (pc - 64);
                const int r = id & 7, kh = (id >> 3) & 1, c = id >> 4;
                if (t) wait_flag(&g_att[r], 32 * t);
                mma_tile64<true>(g_hs_hi, g_hs_lo, 512, g_Whh_hi, g_Whh_lo, 256,
                                 kh ? g_ghp1 : g_ghp0, G4n, r * 64, c * 64,
                                 kh * 128, 128,
                                 kh ? nullptr : bih, kh ? nullptr : bhh);
                flag_add(&g_ghd[r]);
            }
        }

        if (pc < 256) {
            const int rb = pc >> 5;          // rows 2pc, 2pc+1 -> block pc/32
            wait_flag(&g_x1d[rb], 8 * (t + 1));
            attn_half(2 * pc + half, t, htid, enc, y, wt_w, wt_b, Wih,
                      s_x1[half], pv, s_ls[half], s_red[half], &s_yt[half],
                      &g_ghd[rb], 32 * (t + 1));
            flag_add(&g_att[rb]);
        }
    }
}

// ---------------- y_Tp1 head (warp per batch row) ---------------------------
__global__ void __launch_bounds__(256) head1_kernel(float* __restrict__ out) {
    int w = threadIdx.x >> 5, l = threadIdx.x & 31;
    int b = blockIdx.x * 8 + w;
    float sum = 0.0f;
    #pragma unroll
    for (int j = l; j < Pn; j += 32)
        sum += g_hs[b * 512 + j] * g_u[j] + g_ct[b * Mn + j] * g_u[Pn + j];
    #pragma unroll
    for (int o = 16; o > 0; o >>= 1) sum += __shfl_xor_sync(0xffffffffu, sum, o);
    if (l == 0) out[b] = sum + g_u[2 * Pn];
}

// ---------------- extra step e (0 or 1): y_til, LSTM, head ------------------
__global__ void __launch_bounds__(256) extra_step_kernel(
        const float* __restrict__ tar, const int* __restrict__ trainp,
        const float* __restrict__ wt_w, const float* __restrict__ wt_b,
        const float* __restrict__ Wih, float* __restrict__ out, int e) {
    const int b = blockIdx.x, tid = threadIdx.x;
    __shared__ float red8[8];
    __shared__ float s_ytil;

    const float ct = g_ct[b * Mn + tid];
    float dct = block_reduce_256(ct * wt_w[tid], red8);
    if (tid == 0) {
        int train = (trainp[0] != 0);
        float inp = train ? tar[b * 2 + e] : out[e * Bn + b];
        s_ytil = dct + inp * wt_w[Mn] + wt_b[0];
    }
    __syncthreads();
    const float ytil = s_ytil;

    const float* gh0 = &g_ghp0[(size_t)b * G4n];
    const float* gh1 = &g_ghp1[(size_t)b * G4n];
    float ig = gh0[tid]        + gh1[tid]        + ytil * Wih[tid];
    float fg = gh0[tid + Pn]   + gh1[tid + Pn]   + ytil * Wih[tid + Pn];
    float gg = gh0[tid + 2*Pn] + gh1[tid + 2*Pn] + ytil * Wih[tid + 2*Pn];
    float og = gh0[tid + 3*Pn] + gh1[tid + 3*Pn] + ytil * Wih[tid + 3*Pn];
    float so = g_hs[b * 512 + 256 + tid];
    float cn = sigm(fg) * so + sigm(ig) * tanh_acc(gg);
    float hn = sigm(og) * tanh_acc(cn);
    g_hs[b * 512 + 256 + tid] = cn;
    g_hs[b * 512 + tid]       = hn;
    split_store(hn, &g_hs_hi[b * 512 + tid],       &g_hs_lo[b * 512 + tid]);
    split_store(cn, &g_hs_hi[b * 512 + 256 + tid], &g_hs_lo[b * 512 + 256 + tid]);

    float tot = block_reduce_256(hn * g_u[tid] + ct * g_u[Pn + tid], red8);
    if (tid == 0) out[(e + 1) * Bn + b] = tot + g_u[2 * Pn];
}

// ---------------- launcher --------------------------------------------------
extern "C" void kernel_launch(void* const* d_in, const int* in_sizes, int n_in,
                              void* d_out, int out_size) {
    const float* enc   = (const float*)d_in[0];
    const float* y     = (const float*)d_in[1];
    const float* tar   = (const float*)d_in[2];
    const int*   train = (const int*)  d_in[3];
    const float* Wd_w  = (const float*)d_in[4];
    const float* Wd_b  = (const float*)d_in[5];
    const float* Ud_w  = (const float*)d_in[6];
    const float* vd_w  = (const float*)d_in[7];
    const float* wt_w  = (const float*)d_in[8];
    const float* wt_b  = (const float*)d_in[9];
    const float* Wy_w  = (const float*)d_in[10];
    const float* Wy_b  = (const float*)d_in[11];
    const float* vy_w  = (const float*)d_in[12];
    const float* vy_b  = (const float*)d_in[13];
    const float* Wih   = (const float*)d_in[14];
    const float* Whh   = (const float*)d_in[15];
    const float* bih   = (const float*)d_in[16];
    const float* bhh   = (const float*)d_in[17];
    float* out = (float*)d_out;

    conv_enc_kernel<<<8192, 256>>>(enc);                 // launch 1
    conv_weights_kernel<<<1024, 256>>>(Wd_w, Whh, Ud_w); // launch 2 (+init)
    y1_mma_kernel<<<dim3(512, 4), 256>>>();              // launch 3

    persist_kernel<<<NC, 256>>>(enc, y, vd_w, wt_w, wt_b, Wih, Wd_b, bih, bhh); // launch 4

    compute_u_kernel<<<64, 256>>>(vy_w, Wy_w, Wy_b, vy_b);
    head1_kernel<<<Bn / 8, 256>>>(out);

    for (int e = 0; e < 2; e++) {
        step_gemm_gh<<<dim3(8, 32), 256>>>(bih, bhh);
        extra_step_kernel<<<Bn, 256>>>(tar, train, wt_w, wt_b, Wih, out, e);
    }
}

// round 15
// speedup vs baseline: 1.0107x; 1.0107x over previous
#include <cuda_runtime.h>
#include <cuda_bf16.h>
#include <cuda_fp16.h>
#include <cstdint>

#define Bn   512
#define Tn   64
#define Mn   256
#define Pn   256
#define G4n  1024
#define NC   296            // persistent grid: 2 CTAs per SM, all co-resident

// ---------------- device-global scratch (allocation-free) -------------------
__device__ __align__(256) __half g_y1h [Bn * Tn * Mn]; // y1 fp16 (fp32 3-plane acc)
__device__ __align__(256) float g_hs [Bn * 2 * Pn];  // [h | s], lda=512 (fp32 truth)
__device__ __align__(256) float g_ct [Bn * Mn];
__device__ __align__(256) float g_x1p0[Bn * Mn];     // split-K partials of x1
__device__ __align__(256) float g_x1p1[Bn * Mn];
__device__ __align__(256) float g_ghp0[Bn * G4n];    // split-K partials of gh
__device__ __align__(256) float g_ghp1[Bn * G4n];
__device__ __align__(256) float g_u  [2 * Pn + 1];

// per-row-block producer/consumer flags (8 blocks of 64 batch rows)
__device__ int g_x1d[8];    // x1 tasks done (8 per block per step)
__device__ int g_ghd[8];    // gh tasks done (32 per block per step)
__device__ int g_att[8];    // attn CTA arrivals (32 per block per step)

// bf16 hi/lo split operands for tensor-core GEMMs
__device__ __align__(256) __nv_bfloat16 g_hs_hi [Bn * 2 * Pn];
__device__ __align__(256) __nv_bfloat16 g_hs_lo [Bn * 2 * Pn];
__device__ __align__(256) __nv_bfloat16 g_Wd_hi [Mn * 2 * Pn];
__device__ __align__(256) __nv_bfloat16 g_Wd_lo [Mn * 2 * Pn];
__device__ __align__(256) __nv_bfloat16 g_Whh_hi[G4n * Pn];
__device__ __align__(256) __nv_bfloat16 g_Whh_lo[G4n * Pn];
__device__ __align__(256) __nv_bfloat16 g_Ud_hi [Mn * Mn];
__device__ __align__(256) __nv_bfloat16 g_Ud_lo [Mn * Mn];
__device__ __align__(256) __nv_bfloat16 g_enc_hi[Bn * Tn * Mn];
__device__ __align__(256) __nv_bfloat16 g_enc_lo[Bn * Tn * Mn];

// ---------------- math helpers ---------------------------------------------
__device__ __forceinline__ float tanh_acc(float x) {        // accurate (LSTM)
    float e = __expf(2.0f * x);
    return 1.0f - __fdividef(2.0f, e + 1.0f);
}
__device__ __forceinline__ float tanh_fast(float x) {       // MUFU.TANH (attn)
    float r;
    asm("tanh.approx.f32 %0, %1;" : "=f"(r) : "f"(x));
    return r;
}
__device__ __forceinline__ float sigm(float x) {
    return __fdividef(1.0f, 1.0f + __expf(-x));
}
__device__ __forceinline__ float block_reduce_256(float v, float* red8) {
    #pragma unroll
    for (int o = 16; o > 0; o >>= 1) v += __shfl_xor_sync(0xffffffffu, v, o);
    int w = threadIdx.x >> 5, l = threadIdx.x & 31;
    __syncthreads();
    if (l == 0) red8[w] = v;
    __syncthreads();
    float r = red8[0];
    #pragma unroll
    for (int i = 1; i < 8; i++) r += red8[i];
    return r;
}
__device__ __forceinline__ void split_store(float v, __nv_bfloat16* hi,
                                            __nv_bfloat16* lo) {
    __nv_bfloat16 h = __float2bfloat16(v);
    *hi = h;
    *lo = __float2bfloat16(v - __bfloat162float(h));
}
__device__ __forceinline__ void split_store2(float vx, float vy,
                                             __nv_bfloat16* hi, __nv_bfloat16* lo) {
    __nv_bfloat16 hx = __float2bfloat16(vx), hy = __float2bfloat16(vy);
    __nv_bfloat162 h2; h2.x = hx; h2.y = hy;
    *(__nv_bfloat162*)hi = h2;
    __nv_bfloat162 l2;
    l2.x = __float2bfloat16(vx - __bfloat162float(hx));
    l2.y = __float2bfloat16(vy - __bfloat162float(hy));
    *(__nv_bfloat162*)lo = l2;
}

// ---------------- flag sync primitives --------------------------------------
__device__ __forceinline__ void wait_flag(const int* p, int target) {
    if (threadIdx.x == 0) {
        while (*(volatile const int*)p < target) __nanosleep(20);
    }
    __syncthreads();
}
__device__ __forceinline__ void flag_add(int* p) {
    __threadfence();            // per-thread release of prior stores
    __syncthreads();
    if (threadIdx.x == 0) atomicAdd(p, 1);
}

// ---------------- mma / ldmatrix / cp.async primitives ----------------------
__device__ __forceinline__ void ldm4(uint32_t* r, uint32_t addr) {
    asm volatile("ldmatrix.sync.aligned.m8n8.x4.shared.b16 {%0,%1,%2,%3}, [%4];"
        : "=r"(r[0]), "=r"(r[1]), "=r"(r[2]), "=r"(r[3]) : "r"(addr));
}
__device__ __forceinline__ void mma_bf16(float* d, const uint32_t* a,
                                         uint32_t b0, uint32_t b1) {
    asm volatile(
        "mma.sync.aligned.m16n8k16.row.col.f32.bf16.bf16.f32 "
        "{%0,%1,%2,%3}, {%4,%5,%6,%7}, {%8,%9}, {%0,%1,%2,%3};"
        : "+f"(d[0]), "+f"(d[1]), "+f"(d[2]), "+f"(d[3])
        : "r"(a[0]), "r"(a[1]), "r"(a[2]), "r"(a[3]), "r"(b0), "r"(b1));
}
template<bool CG>
__device__ __forceinline__ void cpa16(uint32_t dst, const void* src) {
    if (CG)
        asm volatile("cp.async.cg.shared.global [%0], [%1], 16;\n"
                     :: "r"(dst), "l"(src));
    else
        asm volatile("cp.async.ca.shared.global [%0], [%1], 16;\n"
                     :: "r"(dst), "l"(src));
}
__device__ __forceinline__ void cpa_commit() {
    asm volatile("cp.async.commit_group;\n");
}

// ---------------- conversions (init merged) ----------------------------------
__global__ void conv_enc_kernel(const float* __restrict__ enc) {
    size_t i = ((size_t)blockIdx.x * 256 + threadIdx.x) * 4;
    float4 v = *(const float4*)&enc[i];
    __nv_bfloat16 h[4], l[4];
    float vv[4] = {v.x, v.y, v.z, v.w};
    #pragma unroll
    for (int q = 0; q < 4; q++) {
        h[q] = __float2bfloat16(vv[q]);
        l[q] = __float2bfloat16(vv[q] - __bfloat162float(h[q]));
    }
    __nv_bfloat162 ph0, ph1, pl0, pl1;
    ph0.x = h[0]; ph0.y = h[1]; ph1.x = h[2]; ph1.y = h[3];
    pl0.x = l[0]; pl0.y = l[1]; pl1.x = l[2]; pl1.y = l[3];
    *(__nv_bfloat162*)&g_enc_hi[i]     = ph0;
    *(__nv_bfloat162*)&g_enc_hi[i + 2] = ph1;
    *(__nv_bfloat162*)&g_enc_lo[i]     = pl0;
    *(__nv_bfloat162*)&g_enc_lo[i + 2] = pl1;
}
__global__ void conv_weights_kernel(const float* __restrict__ Wd,
                                    const float* __restrict__ Whh,
                                    const float* __restrict__ Ud) {
    int i = blockIdx.x * 256 + threadIdx.x;
    if (i < Mn * 2 * Pn) split_store(Wd[i], &g_Wd_hi[i], &g_Wd_lo[i]);
    if (i < G4n * Pn)    split_store(Whh[i], &g_Whh_hi[i], &g_Whh_lo[i]);
    if (i < Mn * Mn)     split_store(Ud[i],  &g_Ud_hi[i],  &g_Ud_lo[i]);
    if (i < Bn * 2 * Pn) {                    // merged state init
        g_hs[i] = 0.0f;
        g_hs_hi[i] = __float2bfloat16(0.0f);
        g_hs_lo[i] = __float2bfloat16(0.0f);
    }
    if (i < 8) { g_x1d[i] = 0; g_ghd[i] = 0; g_att[i] = 0; }
}

// ---------------- fold head (parallel): u = vy_w @ Wy_w ----------------------
__global__ void __launch_bounds__(256) compute_u_kernel(
        const float* __restrict__ vy_w, const float* __restrict__ Wy_w,
        const float* __restrict__ Wy_b, const float* __restrict__ vy_b) {
    const int w = threadIdx.x >> 5, l = threadIdx.x & 31;
    const int j = blockIdx.x * 8 + w;
    float s = 0.0f;
    #pragma unroll
    for (int n = l; n < Pn; n += 32) s += vy_w[n] * Wy_w[n * 512 + j];
    #pragma unroll
    for (int o = 16; o > 0; o >>= 1) s += __shfl_xor_sync(0xffffffffu, s, o);
    if (l == 0) g_u[j] = s;

    if (blockIdx.x == 0 && w == 0) {
        float v = 0.0f;
        #pragma unroll
        for (int n = l; n < Pn; n += 32) v += vy_w[n] * Wy_b[n];
        #pragma unroll
        for (int o = 16; o > 0; o >>= 1) v += __shfl_xor_sync(0xffffffffu, v, o);
        if (l == 0) g_u[2 * Pn] = v + vy_b[0];
    }
}

// ---------------- split-bf16 MMA 64x64 tile, cp.async double-buffered -------
#define ST    40
#define PLB   (64 * ST * 2)          // bytes per plane  (5120)
#define BUFB  (4 * PLB)              // bytes per buffer (20480)

// OUT16: store fp16 results to Ch (no bias) instead of fp32 to Cf.
template<bool ACG, bool OUT16>
__device__ __forceinline__ void mma_tile64(
    const __nv_bfloat16* __restrict__ Ah, const __nv_bfloat16* __restrict__ Al,
    int lda,
    const __nv_bfloat16* __restrict__ Bh, const __nv_bfloat16* __restrict__ Bl,
    int ldb,
    float* __restrict__ Cf, __half* __restrict__ Ch,
    int ldc, int r0, int c0, int k0, int K,
    const float* __restrict__ b1, const float* __restrict__ b2)
{
    __shared__ __align__(16) __nv_bfloat16 sm[2 * 4 * 64 * ST];
    const int tid = threadIdx.x;
    const int wid = tid >> 5, lane = tid & 31;
    const int wr = wid & 3, wc = wid >> 2;
    const uint32_t sb = (uint32_t)__cvta_generic_to_shared(sm);

    const int row = tid >> 2, ko = (tid & 3) * 8;
    const __nv_bfloat16* pAh = Ah + (size_t)(r0 + row) * lda + k0 + ko;
    const __nv_bfloat16* pAl = Al + (size_t)(r0 + row) * lda + k0 + ko;
    const __nv_bfloat16* pBh = Bh + (size_t)(c0 + row) * ldb + k0 + ko;
    const __nv_bfloat16* pBl = Bl + (size_t)(c0 + row) * ldb + k0 + ko;
    const uint32_t dA = sb + (uint32_t)(row * ST + ko) * 2;

    float acc[4][4];
    #pragma unroll
    for (int n = 0; n < 4; n++)
        #pragma unroll
        for (int i = 0; i < 4; i++) acc[n][i] = 0.0f;

    const int grp = lane >> 3, lr = lane & 7;
    const uint32_t aAddr = sb +
        (uint32_t)((wr * 16 + ((grp & 1) << 3) + lr) * ST + ((grp >> 1) << 3)) * 2;
    const uint32_t bAddr = sb + 2 * PLB +
        (uint32_t)((wc * 32 + ((grp >> 1) << 3) + lr) * ST + ((grp & 1) << 3)) * 2;

    const int nch = K >> 5;
    {
        cpa16<ACG>(dA,            pAh);
        cpa16<ACG>(dA + PLB,      pAl);
        cpa16<false>(dA + 2 * PLB,  pBh);
        cpa16<false>(dA + 3 * PLB,  pBl);
        cpa_commit();
    }
    for (int c = 0; c < nch; c++) {
        if (c + 1 < nch) {
            const int kb = (c + 1) * 32;
            const uint32_t d = dA + ((c + 1) & 1) * BUFB;
            cpa16<ACG>(d,           pAh + kb);
            cpa16<ACG>(d + PLB,     pAl + kb);
            cpa16<false>(d + 2 * PLB, pBh + kb);
            cpa16<false>(d + 3 * PLB, pBl + kb);
            cpa_commit();
            asm volatile("cp.async.wait_group 1;\n");
        } else {
            asm volatile("cp.async.wait_group 0;\n");
        }
        __syncthreads();
        const uint32_t bo = (c & 1) * BUFB;
        #pragma unroll
        for (int kk = 0; kk < 32; kk += 16) {
            uint32_t ah[4], al[4], bh[2][4], bl[2][4];
            ldm4(ah,   aAddr + bo + kk * 2);
            ldm4(al,   aAddr + bo + PLB + kk * 2);
            ldm4(bh[0], bAddr + bo + kk * 2);
            ldm4(bh[1], bAddr + bo + 16 * ST * 2 + kk * 2);
            ldm4(bl[0], bAddr + bo + PLB + kk * 2);
            ldm4(bl[1], bAddr + bo + PLB + 16 * ST * 2 + kk * 2);
            #pragma unroll
            for (int nt = 0; nt < 4; nt++) {
                const int p = nt >> 1, q = (nt & 1) * 2;
                mma_bf16(acc[nt], ah, bh[p][q], bh[p][q + 1]);   // hi*hi
                mma_bf16(acc[nt], ah, bl[p][q], bl[p][q + 1]);   // hi*lo
                mma_bf16(acc[nt], al, bh[p][q], bh[p][q + 1]);   // lo*hi
            }
        }
        __syncthreads();
    }

    const int rl = lane >> 2, cl = (lane & 3) * 2;
    const int gr = r0 + wr * 16 + rl;
    #pragma unroll
    for (int nt = 0; nt < 4; nt++) {
        const int gc = c0 + wc * 32 + nt * 8 + cl;
        if (OUT16) {
            __half2 v0, v1;
            v0.x = __float2half_rn(acc[nt][0]);
            v0.y = __float2half_rn(acc[nt][1]);
            v1.x = __float2half_rn(acc[nt][2]);
            v1.y = __float2half_rn(acc[nt][3]);
            *(__half2*)&Ch[(size_t)gr * ldc + gc]       = v0;
            *(__half2*)&Ch[(size_t)(gr + 8) * ldc + gc] = v1;
        } else {
            float v0 = 0.0f, v1 = 0.0f;
            if (b1) { v0 += b1[gc]; v1 += b1[gc + 1]; }
            if (b2) { v0 += b2[gc]; v1 += b2[gc + 1]; }
            Cf[(size_t)gr * ldc + gc]           = acc[nt][0] + v0;
            Cf[(size_t)gr * ldc + gc + 1]       = acc[nt][1] + v1;
            Cf[(size_t)(gr + 8) * ldc + gc]     = acc[nt][2] + v0;
            Cf[(size_t)(gr + 8) * ldc + gc + 1] = acc[nt][3] + v1;
        }
    }
}

// y1h = fp16( enc(32768x256) @ Ud^T(256x256) ), fp32 3-plane accumulate
__global__ void __launch_bounds__(256) y1_mma_kernel() {
    mma_tile64<false, true>(g_enc_hi, g_enc_lo, Mn, g_Ud_hi, g_Ud_lo, Mn,
                            nullptr, g_y1h, Mn,
                            blockIdx.x * 64, blockIdx.y * 64, 0, Mn,
                            nullptr, nullptr);
}

// gh-only GEMM for the 2 extra steps (split-K x2; grid (8,32))
__global__ void __launch_bounds__(256) step_gemm_gh(
        const float* __restrict__ bih, const float* __restrict__ bhh) {
    const int r0 = blockIdx.x * 64;
    const int kh = blockIdx.y & 1, ct = blockIdx.y >> 1;
    mma_tile64<false, false>(g_hs_hi, g_hs_lo, 512, g_Whh_hi, g_Whh_lo, 256,
                             kh ? g_ghp1 : g_ghp0, nullptr, G4n,
                             r0, ct * 64, kh * 128, 128,
                             kh ? nullptr : bih, kh ? nullptr : bhh);
}

// ---------------- attention + LSTM: one row per 128-thread half --------------
__device__ __forceinline__ void attn_half(
        int b, int t_step, int htid,
        const float* __restrict__ enc, const float* __restrict__ y,
        const float* __restrict__ wt_w, const float* __restrict__ wt_b,
        const float* __restrict__ Wih,
        float* x1s, const float* pv, float* ls, float* red4, float* ytilp,
        const int* ghflag, int ghtarget) {
    const int w = htid >> 5, l = htid & 31;     // warp 0..3 within half
    const int m0 = 2 * htid;                    // contiguous column pair

    {
        float2 xa = __ldcg((const float2*)&g_x1p0[b * Mn + m0]);
        float2 xb = __ldcg((const float2*)&g_x1p1[b * Mn + m0]);
        x1s[m0]     = xa.x + xb.x;
        x1s[m0 + 1] = xa.y + xb.y;
    }
    __syncthreads();

    // register-cache x1 for this lane's 4 pairs
    float px[8];
    #pragma unroll
    for (int j = 0; j < 4; j++) {
        int p = l + 32 * j;
        float2 xv = *(const float2*)&x1s[2 * p];
        px[2 * j]     = xv.x;
        px[2 * j + 1] = xv.y;
    }

    // logits: warp w -> 16 t; coalesced fp16 half2 y1 loads
    const __half2* yrow0 = (const __half2*)&g_y1h[((size_t)b * Tn + w * 16) * Mn];
    #pragma unroll
    for (int idx = 0; idx < 16; idx++) {
        const __half2* yrow = yrow0 + idx * (Mn / 2);
        float sum = 0.0f;
        #pragma unroll
        for (int j = 0; j < 4; j++) {
            int p = l + 32 * j;
            float2 yv = __half22float2(yrow[p]);
            sum += tanh_fast(px[2 * j]     + yv.x) * pv[2 * j];
            sum += tanh_fast(px[2 * j + 1] + yv.y) * pv[2 * j + 1];
        }
        #pragma unroll
        for (int o = 16; o > 0; o >>= 1) sum += __shfl_xor_sync(0xffffffffu, sum, o);
        if (l == 0) ls[w * 16 + idx] = sum;
    }
    __syncthreads();

    if (w == 0) {                          // softmax over T=64 (warp 0 of half)
        float a = ls[l], c = ls[l + 32];
        float mx = fmaxf(a, c);
        #pragma unroll
        for (int o = 16; o > 0; o >>= 1) mx = fmaxf(mx, __shfl_xor_sync(0xffffffffu, mx, o));
        float e0 = __expf(a - mx), e1 = __expf(c - mx);
        float ts = e0 + e1;
        #pragma unroll
        for (int o = 16; o > 0; o >>= 1) ts += __shfl_xor_sync(0xffffffffu, ts, o);
        float inv = __fdividef(1.0f, ts);
        ls[l]      = e0 * inv;
        ls[l + 32] = e1 * inv;
    }
    __syncthreads();

    // context: fp32 enc, contiguous float2 per thread (accuracy-critical)
    float a0 = 0.0f, a1 = 0.0f;
    const float* encb = &enc[(size_t)b * Tn * Mn];
    #pragma unroll 8
    for (int t = 0; t < Tn; t++) {
        float beta = ls[t];
        float2 ev = *(const float2*)&encb[t * Mn + m0];
        a0 += beta * ev.x;
        a1 += beta * ev.y;
    }
    *(float2*)&g_ct[b * Mn + m0] = make_float2(a0, a1);

    // y_til reduce over 256 (2 per thread, 4 warps)
    {
        float2 wv = *(const float2*)&wt_w[m0];
        float v = a0 * wv.x + a1 * wv.y;
        #pragma unroll
        for (int o = 16; o > 0; o >>= 1) v += __shfl_xor_sync(0xffffffffu, v, o);
        if (l == 0) red4[w] = v;
    }
    __syncthreads();
    if (htid == 0)
        *ytilp = red4[0] + red4[1] + red4[2] + red4[3]
               + y[b * Tn + t_step] * wt_w[Mn] + wt_b[0];
    __syncthreads();
    const float ytil = *ytilp;

    // wait for this row-block's gh tasks (overlapped with phases above)
    if (threadIdx.x == 0) {
        while (*(volatile const int*)ghflag < ghtarget) __nanosleep(20);
    }
    __syncthreads();

    // LSTM cell for the column pair (i,f,g,o; biases folded into ghp0)
    const float* gh0 = &g_ghp0[(size_t)b * G4n];
    const float* gh1 = &g_ghp1[(size_t)b * G4n];
    float2 ig, fg, gg, og;
    {
        float2 a = __ldcg((const float2*)(gh0 + m0));
        float2 c = __ldcg((const float2*)(gh1 + m0));
        float2 wv = *(const float2*)(Wih + m0);
        ig = make_float2(a.x + c.x + ytil * wv.x, a.y + c.y + ytil * wv.y);
    }
    {
        float2 a = __ldcg((const float2*)(gh0 + Pn + m0));
        float2 c = __ldcg((const float2*)(gh1 + Pn + m0));
        float2 wv = *(const float2*)(Wih + Pn + m0);
        fg = make_float2(a.x + c.x + ytil * wv.x, a.y + c.y + ytil * wv.y);
    }
    {
        float2 a = __ldcg((const float2*)(gh0 + 2 * Pn + m0));
        float2 c = __ldcg((const float2*)(gh1 + 2 * Pn + m0));
        float2 wv = *(const float2*)(Wih + 2 * Pn + m0);
        gg = make_float2(a.x + c.x + ytil * wv.x, a.y + c.y + ytil * wv.y);
    }
    {
        float2 a = __ldcg((const float2*)(gh0 + 3 * Pn + m0));
        float2 c = __ldcg((const float2*)(gh1 + 3 * Pn + m0));
        float2 wv = *(const float2*)(Wih + 3 * Pn + m0);
        og = make_float2(a.x + c.x + ytil * wv.x, a.y + c.y + ytil * wv.y);
    }
    float2 so = *(const float2*)&g_hs[b * 512 + 256 + m0];  // CTA-local state
    float cnx = sigm(fg.x) * so.x + sigm(ig.x) * tanh_acc(gg.x);
    float cny = sigm(fg.y) * so.y + sigm(ig.y) * tanh_acc(gg.y);
    float hnx = sigm(og.x) * tanh_acc(cnx);
    float hny = sigm(og.y) * tanh_acc(cny);
    *(float2*)&g_hs[b * 512 + 256 + m0] = make_float2(cnx, cny);
    *(float2*)&g_hs[b * 512 + m0]       = make_float2(hnx, hny);
    split_store2(hnx, hny, &g_hs_hi[b * 512 + m0],       &g_hs_lo[b * 512 + m0]);
    split_store2(cnx, cny, &g_hs_hi[b * 512 + 256 + m0], &g_hs_lo[b * 512 + 256 + m0]);
}

// ---------------- persistent 64-step loop, flag-pipelined --------------------
__global__ void __launch_bounds__(256, 2) persist_kernel(
        const float* __restrict__ enc, const float* __restrict__ y,
        const float* __restrict__ vd_w, const float* __restrict__ wt_w,
        const float* __restrict__ wt_b, const float* __restrict__ Wih,
        const float* __restrict__ Wd_b, const float* __restrict__ bih,
        const float* __restrict__ bhh) {
    __shared__ float s_x1[2][Mn], s_v[Mn], s_ls[2][Tn], s_red[2][4], s_yt[2];
    s_v[threadIdx.x] = vd_w[threadIdx.x];    // loop-invariant
    __syncthreads();

    const int pc   = blockIdx.x;
    const int half = threadIdx.x >> 7;       // 0 or 1
    const int htid = threadIdx.x & 127;

    // register-cache v for this lane's 4 pairs (same mapping as px)
    float pv[8];
    {
        const int l = htid & 31;
        #pragma unroll
        for (int j = 0; j < 4; j++) {
            int p = l + 32 * j;
            float2 vv = *(const float2*)&s_v[2 * p];
            pv[2 * j]     = vv.x;
            pv[2 * j + 1] = vv.y;
        }
    }

    for (int t = 0; t < Tn; t++) {
        if (pc < 64) {
            const int r = pc & 7, kh = (pc >> 3) & 1, c = pc >> 4;
            if (t) wait_flag(&g_att[r], 32 * t);
            mma_tile64<true, false>(g_hs_hi, g_hs_lo, 512, g_Wd_hi, g_Wd_lo, 512,
                             kh ? g_x1p1 : g_x1p0, nullptr, Mn, r * 64, c * 64,
                             kh * 256, 256, kh ? nullptr : Wd_b, nullptr);
            flag_add(&g_x1d[r]);
        } else {
            int id = pc - 64;
            {
                const int r = id & 7, kh = (id >> 3) & 1, c = id >> 4;
                if (t) wait_flag(&g_att[r], 32 * t);
                mma_tile64<true, false>(g_hs_hi, g_hs_lo, 512, g_Whh_hi, g_Whh_lo, 256,
                                 kh ? g_ghp1 : g_ghp0, nullptr, G4n, r * 64, c * 64,
                                 kh * 128, 128,
                                 kh ? nullptr : bih, kh ? nullptr : bhh);
                flag_add(&g_ghd[r]);
            }
            if (pc < 88) {
                id = 232 + (pc - 64);
                const int r = id & 7, kh = (id >> 3) & 1, c = id >> 4;
                if (t) wait_flag(&g_att[r], 32 * t);
                mma_tile64<true, false>(g_hs_hi, g_hs_lo, 512, g_Whh_hi, g_Whh_lo, 256,
                                 kh ? g_ghp1 : g_ghp0, nullptr, G4n, r * 64, c * 64,
                                 kh * 128, 128,
                                 kh ? nullptr : bih, kh ? nullptr : bhh);
                flag_add(&g_ghd[r]);
            }
        }

        if (pc < 256) {
            const int rb = pc >> 5;          // rows 2pc, 2pc+1 -> block pc/32
            wait_flag(&g_x1d[rb], 8 * (t + 1));
            attn_half(2 * pc + half, t, htid, enc, y, wt_w, wt_b, Wih,
                      s_x1[half], pv, s_ls[half], s_red[half], &s_yt[half],
                      &g_ghd[rb], 32 * (t + 1));
            flag_add(&g_att[rb]);
        }
    }
}

// ---------------- y_Tp1 head (warp per batch row) ---------------------------
__global__ void __launch_bounds__(256) head1_kernel(float* __restrict__ out) {
    int w = threadIdx.x >> 5, l = threadIdx.x & 31;
    int b = blockIdx.x * 8 + w;
    float sum = 0.0f;
    #pragma unroll
    for (int j = l; j < Pn; j += 32)
        sum += g_hs[b * 512 + j] * g_u[j] + g_ct[b * Mn + j] * g_u[Pn + j];
    #pragma unroll
    for (int o = 16; o > 0; o >>= 1) sum += __shfl_xor_sync(0xffffffffu, sum, o);
    if (l == 0) out[b] = sum + g_u[2 * Pn];
}

// ---------------- extra step e (0 or 1): y_til, LSTM, head ------------------
__global__ void __launch_bounds__(256) extra_step_kernel(
        const float* __restrict__ tar, const int* __restrict__ trainp,
        const float* __restrict__ wt_w, const float* __restrict__ wt_b,
        const float* __restrict__ Wih, float* __restrict__ out, int e) {
    const int b = blockIdx.x, tid = threadIdx.x;
    __shared__ float red8[8];
    __shared__ float s_ytil;

    const float ct = g_ct[b * Mn + tid];
    float dct = block_reduce_256(ct * wt_w[tid], red8);
    if (tid == 0) {
        int train = (trainp[0] != 0);
        float inp = train ? tar[b * 2 + e] : out[e * Bn + b];
        s_ytil = dct + inp * wt_w[Mn] + wt_b[0];
    }
    __syncthreads();
    const float ytil = s_ytil;

    const float* gh0 = &g_ghp0[(size_t)b * G4n];
    const float* gh1 = &g_ghp1[(size_t)b * G4n];
    float ig = gh0[tid]        + gh1[tid]        + ytil * Wih[tid];
    float fg = gh0[tid + Pn]   + gh1[tid + Pn]   + ytil * Wih[tid + Pn];
    float gg = gh0[tid + 2*Pn] + gh1[tid + 2*Pn] + ytil * Wih[tid + 2*Pn];
    float og = gh0[tid + 3*Pn] + gh1[tid + 3*Pn] + ytil * Wih[tid + 3*Pn];
    float so = g_hs[b * 512 + 256 + tid];
    float cn = sigm(fg) * so + sigm(ig) * tanh_acc(gg);
    float hn = sigm(og) * tanh_acc(cn);
    g_hs[b * 512 + 256 + tid] = cn;
    g_hs[b * 512 + tid]       = hn;
    split_store(hn, &g_hs_hi[b * 512 + tid],       &g_hs_lo[b * 512 + tid]);
    split_store(cn, &g_hs_hi[b * 512 + 256 + tid], &g_hs_lo[b * 512 + 256 + tid]);

    float tot = block_reduce_256(hn * g_u[tid] + ct * g_u[Pn + tid], red8);
    if (tid == 0) out[(e + 1) * Bn + b] = tot + g_u[2 * Pn];
}

// ---------------- launcher --------------------------------------------------
extern "C" void kernel_launch(void* const* d_in, const int* in_sizes, int n_in,
                              void* d_out, int out_size) {
    const float* enc   = (const float*)d_in[0];
    const float* y     = (const float*)d_in[1];
    const float* tar   = (const float*)d_in[2];
    const int*   train = (const int*)  d_in[3];
    const float* Wd_w  = (const float*)d_in[4];
    const float* Wd_b  = (const float*)d_in[5];
    const float* Ud_w  = (const float*)d_in[6];
    const float* vd_w  = (const float*)d_in[7];
    const float* wt_w  = (const float*)d_in[8];
    const float* wt_b  = (const float*)d_in[9];
    const float* Wy_w  = (const float*)d_in[10];
    const float* Wy_b  = (const float*)d_in[11];
    const float* vy_w  = (const float*)d_in[12];
    const float* vy_b  = (const float*)d_in[13];
    const float* Wih   = (const float*)d_in[14];
    const float* Whh   = (const float*)d_in[15];
    const float* bih   = (const float*)d_in[16];
    const float* bhh   = (const float*)d_in[17];
    float* out = (float*)d_out;

    conv_enc_kernel<<<8192, 256>>>(enc);                 // launch 1
    conv_weights_kernel<<<1024, 256>>>(Wd_w, Whh, Ud_w); // launch 2 (+init)
    y1_mma_kernel<<<dim3(512, 4), 256>>>();              // launch 3

    persist_kernel<<<NC, 256>>>(enc, y, vd_w, wt_w, wt_b, Wih, Wd_b, bih, bhh); // launch 4

    compute_u_kernel<<<64, 256>>>(vy_w, Wy_w, Wy_b, vy_b);
    head1_kernel<<<Bn / 8, 256>>>(out);

    for (int e = 0; e < 2; e++) {
        step_gemm_gh<<<dim3(8, 32), 256>>>(bih, bhh);
        extra_step_kernel<<<Bn, 256>>>(tar, train, wt_w, wt_b, Wih, out, e);
    }
}

// round 17
// speedup vs baseline: 1.0432x; 1.0322x over previous
#include <cuda_runtime.h>
#include <cuda_bf16.h>
#include <cuda_fp16.h>
#include <cstdint>

#define Bn   512
#define Tn   64
#define Mn   256
#define Pn   256
#define G4n  1024
#define NC   296            // persistent grid: 2 CTAs per SM, all co-resident

// ---------------- device-global scratch (allocation-free) -------------------
__device__ __align__(256) __half g_y1h [Bn * Tn * Mn]; // y1 fp16 (fp32 3-plane acc)
__device__ __align__(256) float g_hs [Bn * 2 * Pn];  // [h | s], lda=512 (fp32 truth)
__device__ __align__(256) float g_ct [Bn * Mn];
__device__ __align__(256) float g_x1p0[Bn * Mn];     // split-K partials of x1
__device__ __align__(256) float g_x1p1[Bn * Mn];
__device__ __align__(256) float g_ghp0[Bn * G4n];    // split-K partials of gh
__device__ __align__(256) float g_ghp1[Bn * G4n];
__device__ __align__(256) float g_u  [2 * Pn + 1];
__device__ int g_cnt;                                // barrier arrival counter
__device__ volatile int g_rel;                       // barrier release epoch

// bf16 hi/lo split operands for tensor-core GEMMs
__device__ __align__(256) __nv_bfloat16 g_hs_hi [Bn * 2 * Pn];
__device__ __align__(256) __nv_bfloat16 g_hs_lo [Bn * 2 * Pn];
__device__ __align__(256) __nv_bfloat16 g_Wd_hi [Mn * 2 * Pn];
__device__ __align__(256) __nv_bfloat16 g_Wd_lo [Mn * 2 * Pn];
__device__ __align__(256) __nv_bfloat16 g_Whh_hi[G4n * Pn];
__device__ __align__(256) __nv_bfloat16 g_Whh_lo[G4n * Pn];
__device__ __align__(256) __nv_bfloat16 g_Ud_hi [Mn * Mn];
__device__ __align__(256) __nv_bfloat16 g_Ud_lo [Mn * Mn];
__device__ __align__(256) __nv_bfloat16 g_enc_hi[Bn * Tn * Mn];
__device__ __align__(256) __nv_bfloat16 g_enc_lo[Bn * Tn * Mn];

// ---------------- math helpers ---------------------------------------------
__device__ __forceinline__ float tanh_acc(float x) {        // accurate (LSTM)
    float e = __expf(2.0f * x);
    return 1.0f - __fdividef(2.0f, e + 1.0f);
}
__device__ __forceinline__ float tanh_fast(float x) {       // MUFU.TANH (attn)
    float r;
    asm("tanh.approx.f32 %0, %1;" : "=f"(r) : "f"(x));
    return r;
}
__device__ __forceinline__ float sigm(float x) {
    return __fdividef(1.0f, 1.0f + __expf(-x));
}
__device__ __forceinline__ float block_reduce_256(float v, float* red8) {
    #pragma unroll
    for (int o = 16; o > 0; o >>= 1) v += __shfl_xor_sync(0xffffffffu, v, o);
    int w = threadIdx.x >> 5, l = threadIdx.x & 31;
    __syncthreads();
    if (l == 0) red8[w] = v;
    __syncthreads();
    float r = red8[0];
    #pragma unroll
    for (int i = 1; i < 8; i++) r += red8[i];
    return r;
}
__device__ __forceinline__ void split_store(float v, __nv_bfloat16* hi,
                                            __nv_bfloat16* lo) {
    __nv_bfloat16 h = __float2bfloat16(v);
    *hi = h;
    *lo = __float2bfloat16(v - __bfloat162float(h));
}
__device__ __forceinline__ void split_store2(float vx, float vy,
                                             __nv_bfloat16* hi, __nv_bfloat16* lo) {
    __nv_bfloat16 hx = __float2bfloat16(vx), hy = __float2bfloat16(vy);
    __nv_bfloat162 h2; h2.x = hx; h2.y = hy;
    *(__nv_bfloat162*)hi = h2;
    __nv_bfloat162 l2;
    l2.x = __float2bfloat16(vx - __bfloat162float(hx));
    l2.y = __float2bfloat16(vy - __bfloat162float(hy));
    *(__nv_bfloat162*)lo = l2;
}

// ---------------- grid barrier (sense-release; all CTAs co-resident) --------
__device__ __forceinline__ void grid_barrier(int target) {
    __syncthreads();
    if (threadIdx.x == 0) {
        __threadfence();
        int old = atomicAdd(&g_cnt, 1);
        if (old == target - 1) {
            g_rel = target;                     // release (write-once line)
        } else {
            while (g_rel < target) __nanosleep(20);
        }
        __threadfence();
    }
    __syncthreads();
}

// ---------------- mma / ldmatrix / cp.async primitives ----------------------
__device__ __forceinline__ void ldm4(uint32_t* r, uint32_t addr) {
    asm volatile("ldmatrix.sync.aligned.m8n8.x4.shared.b16 {%0,%1,%2,%3}, [%4];"
        : "=r"(r[0]), "=r"(r[1]), "=r"(r[2]), "=r"(r[3]) : "r"(addr));
}
__device__ __forceinline__ void mma_bf16(float* d, const uint32_t* a,
                                         uint32_t b0, uint32_t b1) {
    asm volatile(
        "mma.sync.aligned.m16n8k16.row.col.f32.bf16.bf16.f32 "
        "{%0,%1,%2,%3}, {%4,%5,%6,%7}, {%8,%9}, {%0,%1,%2,%3};"
        : "+f"(d[0]), "+f"(d[1]), "+f"(d[2]), "+f"(d[3])
        : "r"(a[0]), "r"(a[1]), "r"(a[2]), "r"(a[3]), "r"(b0), "r"(b1));
}
template<bool CG>
__device__ __forceinline__ void cpa16(uint32_t dst, const void* src) {
    if (CG)
        asm volatile("cp.async.cg.shared.global [%0], [%1], 16;\n"
                     :: "r"(dst), "l"(src));
    else
        asm volatile("cp.async.ca.shared.global [%0], [%1], 16;\n"
                     :: "r"(dst), "l"(src));
}
__device__ __forceinline__ void cpa_commit() {
    asm volatile("cp.async.commit_group;\n");
}

// ---------------- conversions (init merged) ----------------------------------
__global__ void conv_enc_kernel(const float* __restrict__ enc) {
    size_t i = ((size_t)blockIdx.x * 256 + threadIdx.x) * 4;
    float4 v = *(const float4*)&enc[i];
    __nv_bfloat16 h[4], l[4];
    float vv[4] = {v.x, v.y, v.z, v.w};
    #pragma unroll
    for (int q = 0; q < 4; q++) {
        h[q] = __float2bfloat16(vv[q]);
        l[q] = __float2bfloat16(vv[q] - __bfloat162float(h[q]));
    }
    __nv_bfloat162 ph0, ph1, pl0, pl1;
    ph0.x = h[0]; ph0.y = h[1]; ph1.x = h[2]; ph1.y = h[3];
    pl0.x = l[0]; pl0.y = l[1]; pl1.x = l[2]; pl1.y = l[3];
    *(__nv_bfloat162*)&g_enc_hi[i]     = ph0;
    *(__nv_bfloat162*)&g_enc_hi[i + 2] = ph1;
    *(__nv_bfloat162*)&g_enc_lo[i]     = pl0;
    *(__nv_bfloat162*)&g_enc_lo[i + 2] = pl1;
}
__global__ void conv_weights_kernel(const float* __restrict__ Wd,
                                    const float* __restrict__ Whh,
                                    const float* __restrict__ Ud) {
    int i = blockIdx.x * 256 + threadIdx.x;
    if (i < Mn * 2 * Pn) split_store(Wd[i], &g_Wd_hi[i], &g_Wd_lo[i]);
    if (i < G4n * Pn)    split_store(Whh[i], &g_Whh_hi[i], &g_Whh_lo[i]);
    if (i < Mn * Mn)     split_store(Ud[i],  &g_Ud_hi[i],  &g_Ud_lo[i]);
    if (i < Bn * 2 * Pn) {                    // merged state init
        g_hs[i] = 0.0f;
        g_hs_hi[i] = __float2bfloat16(0.0f);
        g_hs_lo[i] = __float2bfloat16(0.0f);
    }
    if (i == 0) { g_cnt = 0; g_rel = 0; }
}

// ---------------- fold head (parallel): u = vy_w @ Wy_w ----------------------
__global__ void __launch_bounds__(256) compute_u_kernel(
        const float* __restrict__ vy_w, const float* __restrict__ Wy_w,
        const float* __restrict__ Wy_b, const float* __restrict__ vy_b) {
    const int w = threadIdx.x >> 5, l = threadIdx.x & 31;
    const int j = blockIdx.x * 8 + w;
    float s = 0.0f;
    #pragma unroll
    for (int n = l; n < Pn; n += 32) s += vy_w[n] * Wy_w[n * 512 + j];
    #pragma unroll
    for (int o = 16; o > 0; o >>= 1) s += __shfl_xor_sync(0xffffffffu, s, o);
    if (l == 0) g_u[j] = s;

    if (blockIdx.x == 0 && w == 0) {
        float v = 0.0f;
        #pragma unroll
        for (int n = l; n < Pn; n += 32) v += vy_w[n] * Wy_b[n];
        #pragma unroll
        for (int o = 16; o > 0; o >>= 1) v += __shfl_xor_sync(0xffffffffu, v, o);
        if (l == 0) g_u[2 * Pn] = v + vy_b[0];
    }
}

// ---------------- split-bf16 MMA 64x64 tile, cp.async double-buffered -------
#define ST    40
#define PLB   (64 * ST * 2)          // bytes per plane  (5120)
#define BUFB  (4 * PLB)              // bytes per buffer (20480)

// OUT16: store fp16 results to Ch (no bias) instead of fp32 to Cf.
template<bool ACG, bool OUT16>
__device__ __forceinline__ void mma_tile64(
    const __nv_bfloat16* __restrict__ Ah, const __nv_bfloat16* __restrict__ Al,
    int lda,
    const __nv_bfloat16* __restrict__ Bh, const __nv_bfloat16* __restrict__ Bl,
    int ldb,
    float* __restrict__ Cf, __half* __restrict__ Ch,
    int ldc, int r0, int c0, int k0, int K,
    const float* __restrict__ b1, const float* __restrict__ b2)
{
    __shared__ __align__(16) __nv_bfloat16 sm[2 * 4 * 64 * ST];
    const int tid = threadIdx.x;
    const int wid = tid >> 5, lane = tid & 31;
    const int wr = wid & 3, wc = wid >> 2;
    const uint32_t sb = (uint32_t)__cvta_generic_to_shared(sm);

    const int row = tid >> 2, ko = (tid & 3) * 8;
    const __nv_bfloat16* pAh = Ah + (size_t)(r0 + row) * lda + k0 + ko;
    const __nv_bfloat16* pAl = Al + (size_t)(r0 + row) * lda + k0 + ko;
    const __nv_bfloat16* pBh = Bh + (size_t)(c0 + row) * ldb + k0 + ko;
    const __nv_bfloat16* pBl = Bl + (size_t)(c0 + row) * ldb + k0 + ko;
    const uint32_t dA = sb + (uint32_t)(row * ST + ko) * 2;

    float acc[4][4];
    #pragma unroll
    for (int n = 0; n < 4; n++)
        #pragma unroll
        for (int i = 0; i < 4; i++) acc[n][i] = 0.0f;

    const int grp = lane >> 3, lr = lane & 7;
    const uint32_t aAddr = sb +
        (uint32_t)((wr * 16 + ((grp & 1) << 3) + lr) * ST + ((grp >> 1) << 3)) * 2;
    const uint32_t bAddr = sb + 2 * PLB +
        (uint32_t)((wc * 32 + ((grp >> 1) << 3) + lr) * ST + ((grp & 1) << 3)) * 2;

    const int nch = K >> 5;
    {
        cpa16<ACG>(dA,            pAh);
        cpa16<ACG>(dA + PLB,      pAl);
        cpa16<false>(dA + 2 * PLB,  pBh);
        cpa16<false>(dA + 3 * PLB,  pBl);
        cpa_commit();
    }
    for (int c = 0; c < nch; c++) {
        if (c + 1 < nch) {
            const int kb = (c + 1) * 32;
            const uint32_t d = dA + ((c + 1) & 1) * BUFB;
            cpa16<ACG>(d,           pAh + kb);
            cpa16<ACG>(d + PLB,     pAl + kb);
            cpa16<false>(d + 2 * PLB, pBh + kb);
            cpa16<false>(d + 3 * PLB, pBl + kb);
            cpa_commit();
            asm volatile("cp.async.wait_group 1;\n");
        } else {
            asm volatile("cp.async.wait_group 0;\n");
        }
        __syncthreads();
        const uint32_t bo = (c & 1) * BUFB;
        #pragma unroll
        for (int kk = 0; kk < 32; kk += 16) {
            uint32_t ah[4], al[4], bh[2][4], bl[2][4];
            ldm4(ah,   aAddr + bo + kk * 2);
            ldm4(al,   aAddr + bo + PLB + kk * 2);
            ldm4(bh[0], bAddr + bo + kk * 2);
            ldm4(bh[1], bAddr + bo + 16 * ST * 2 + kk * 2);
            ldm4(bl[0], bAddr + bo + PLB + kk * 2);
            ldm4(bl[1], bAddr + bo + PLB + 16 * ST * 2 + kk * 2);
            #pragma unroll
            for (int nt = 0; nt < 4; nt++) {
                const int p = nt >> 1, q = (nt & 1) * 2;
                mma_bf16(acc[nt], ah, bh[p][q], bh[p][q + 1]);   // hi*hi
                mma_bf16(acc[nt], ah, bl[p][q], bl[p][q + 1]);   // hi*lo
                mma_bf16(acc[nt], al, bh[p][q], bh[p][q + 1]);   // lo*hi
            }
        }
        __syncthreads();
    }

    const int rl = lane >> 2, cl = (lane & 3) * 2;
    const int gr = r0 + wr * 16 + rl;
    #pragma unroll
    for (int nt = 0; nt < 4; nt++) {
        const int gc = c0 + wc * 32 + nt * 8 + cl;
        if (OUT16) {
            __half2 v0, v1;
            v0.x = __float2half_rn(acc[nt][0]);
            v0.y = __float2half_rn(acc[nt][1]);
            v1.x = __float2half_rn(acc[nt][2]);
            v1.y = __float2half_rn(acc[nt][3]);
            *(__half2*)&Ch[(size_t)gr * ldc + gc]       = v0;
            *(__half2*)&Ch[(size_t)(gr + 8) * ldc + gc] = v1;
        } else {
            float v0 = 0.0f, v1 = 0.0f;
            if (b1) { v0 += b1[gc]; v1 += b1[gc + 1]; }
            if (b2) { v0 += b2[gc]; v1 += b2[gc + 1]; }
            Cf[(size_t)gr * ldc + gc]           = acc[nt][0] + v0;
            Cf[(size_t)gr * ldc + gc + 1]       = acc[nt][1] + v1;
            Cf[(size_t)(gr + 8) * ldc + gc]     = acc[nt][2] + v0;
            Cf[(size_t)(gr + 8) * ldc + gc + 1] = acc[nt][3] + v1;
        }
    }
}

// y1h = fp16( enc(32768x256) @ Ud^T(256x256) ), fp32 3-plane accumulate
__global__ void __launch_bounds__(256) y1_mma_kernel() {
    mma_tile64<false, true>(g_enc_hi, g_enc_lo, Mn, g_Ud_hi, g_Ud_lo, Mn,
                            nullptr, g_y1h, Mn,
                            blockIdx.x * 64, blockIdx.y * 64, 0, Mn,
                            nullptr, nullptr);
}

// gh-only GEMM for the 2 extra steps (split-K x2; grid (8,32))
__global__ void __launch_bounds__(256) step_gemm_gh(
        const float* __restrict__ bih, const float* __restrict__ bhh) {
    const int r0 = blockIdx.x * 64;
    const int kh = blockIdx.y & 1, ct = blockIdx.y >> 1;
    mma_tile64<false, false>(g_hs_hi, g_hs_lo, 512, g_Whh_hi, g_Whh_lo, 256,
                             kh ? g_ghp1 : g_ghp0, nullptr, G4n,
                             r0, ct * 64, kh * 128, 128,
                             kh ? nullptr : bih, kh ? nullptr : bhh);
}

// ---------------- attention + LSTM: one row per 128-thread half --------------
__device__ __forceinline__ void attn_half(
        int b, int t_step, int htid,
        const float* __restrict__ enc, const float* __restrict__ y,
        const float* __restrict__ wt_w, const float* __restrict__ wt_b,
        const float* __restrict__ Wih,
        float* x1s, const float* pv, float* ls, float* red4, float* ytilp) {
    const int w = htid >> 5, l = htid & 31;     // warp 0..3 within half
    const int m0 = 2 * htid;                    // contiguous column pair

    {
        float2 xa = __ldcg((const float2*)&g_x1p0[b * Mn + m0]);
        float2 xb = __ldcg((const float2*)&g_x1p1[b * Mn + m0]);
        x1s[m0]     = xa.x + xb.x;
        x1s[m0 + 1] = xa.y + xb.y;
    }
    __syncthreads();

    // register-cache x1 for this lane's 4 pairs
    float px[8];
    #pragma unroll
    for (int j = 0; j < 4; j++) {
        int p = l + 32 * j;
        float2 xv = *(const float2*)&x1s[2 * p];
        px[2 * j]     = xv.x;
        px[2 * j + 1] = xv.y;
    }

    // logits: warp w -> 16 t; coalesced fp16 half2 y1 loads
    const __half2* yrow0 = (const __half2*)&g_y1h[((size_t)b * Tn + w * 16) * Mn];
    #pragma unroll
    for (int idx = 0; idx < 16; idx++) {
        const __half2* yrow = yrow0 + idx * (Mn / 2);
        float sum = 0.0f;
        #pragma unroll
        for (int j = 0; j < 4; j++) {
            int p = l + 32 * j;
            float2 yv = __half22float2(yrow[p]);
            sum += tanh_fast(px[2 * j]     + yv.x) * pv[2 * j];
            sum += tanh_fast(px[2 * j + 1] + yv.y) * pv[2 * j + 1];
        }
        #pragma unroll
        for (int o = 16; o > 0; o >>= 1) sum += __shfl_xor_sync(0xffffffffu, sum, o);
        if (l == 0) ls[w * 16 + idx] = sum;
    }
    __syncthreads();

    if (w == 0) {                          // softmax over T=64 (warp 0 of half)
        float a = ls[l], c = ls[l + 32];
        float mx = fmaxf(a, c);
        #pragma unroll
        for (int o = 16; o > 0; o >>= 1) mx = fmaxf(mx, __shfl_xor_sync(0xffffffffu, mx, o));
        float e0 = __expf(a - mx), e1 = __expf(c - mx);
        float ts = e0 + e1;
        #pragma unroll
        for (int o = 16; o > 0; o >>= 1) ts += __shfl_xor_sync(0xffffffffu, ts, o);
        float inv = __fdividef(1.0f, ts);
        ls[l]      = e0 * inv;
        ls[l + 32] = e1 * inv;
    }
    __syncthreads();

    // context: fp32 enc, contiguous float2 per thread (accuracy-critical)
    float a0 = 0.0f, a1 = 0.0f;
    const float* encb = &enc[(size_t)b * Tn * Mn];
    #pragma unroll 8
    for (int t = 0; t < Tn; t++) {
        float beta = ls[t];
        float2 ev = *(const float2*)&encb[t * Mn + m0];
        a0 += beta * ev.x;
        a1 += beta * ev.y;
    }
    *(float2*)&g_ct[b * Mn + m0] = make_float2(a0, a1);

    // y_til reduce over 256 (2 per thread, 4 warps)
    {
        float2 wv = *(const float2*)&wt_w[m0];
        float v = a0 * wv.x + a1 * wv.y;
        #pragma unroll
        for (int o = 16; o > 0; o >>= 1) v += __shfl_xor_sync(0xffffffffu, v, o);
        if (l == 0) red4[w] = v;
    }
    __syncthreads();
    if (htid == 0)
        *ytilp = red4[0] + red4[1] + red4[2] + red4[3]
               + y[b * Tn + t_step] * wt_w[Mn] + wt_b[0];
    __syncthreads();
    const float ytil = *ytilp;

    // LSTM cell for the column pair (i,f,g,o; biases folded into ghp0)
    const float* gh0 = &g_ghp0[(size_t)b * G4n];
    const float* gh1 = &g_ghp1[(size_t)b * G4n];
    float2 ig, fg, gg, og;
    {
        float2 a = __ldcg((const float2*)(gh0 + m0));
        float2 c = __ldcg((const float2*)(gh1 + m0));
        float2 wv = *(const float2*)(Wih + m0);
        ig = make_float2(a.x + c.x + ytil * wv.x, a.y + c.y + ytil * wv.y);
    }
    {
        float2 a = __ldcg((const float2*)(gh0 + Pn + m0));
        float2 c = __ldcg((const float2*)(gh1 + Pn + m0));
        float2 wv = *(const float2*)(Wih + Pn + m0);
        fg = make_float2(a.x + c.x + ytil * wv.x, a.y + c.y + ytil * wv.y);
    }
    {
        float2 a = __ldcg((const float2*)(gh0 + 2 * Pn + m0));
        float2 c = __ldcg((const float2*)(gh1 + 2 * Pn + m0));
        float2 wv = *(const float2*)(Wih + 2 * Pn + m0);
        gg = make_float2(a.x + c.x + ytil * wv.x, a.y + c.y + ytil * wv.y);
    }
    {
        float2 a = __ldcg((const float2*)(gh0 + 3 * Pn + m0));
        float2 c = __ldcg((const float2*)(gh1 + 3 * Pn + m0));
        float2 wv = *(const float2*)(Wih + 3 * Pn + m0);
        og = make_float2(a.x + c.x + ytil * wv.x, a.y + c.y + ytil * wv.y);
    }
    float2 so = *(const float2*)&g_hs[b * 512 + 256 + m0];  // CTA-local state
    float cnx = sigm(fg.x) * so.x + sigm(ig.x) * tanh_acc(gg.x);
    float cny = sigm(fg.y) * so.y + sigm(ig.y) * tanh_acc(gg.y);
    float hnx = sigm(og.x) * tanh_acc(cnx);
    float hny = sigm(og.y) * tanh_acc(cny);
    *(float2*)&g_hs[b * 512 + 256 + m0] = make_float2(cnx, cny);
    *(float2*)&g_hs[b * 512 + m0]       = make_float2(hnx, hny);
    split_store2(hnx, hny, &g_hs_hi[b * 512 + m0],       &g_hs_lo[b * 512 + m0]);
    split_store2(cnx, cny, &g_hs_hi[b * 512 + 256 + m0], &g_hs_lo[b * 512 + 256 + m0]);
}

// ---------------- persistent 64-step loop, global sense-barriers -------------
// GEMM tasks balanced: x1 (64 tasks, K=256) -> CTAs 0..63 (1 each);
// gh (256 tasks, K=128) -> CTAs 64..295 (1 each) + CTAs 64..87 (2nd task).
__global__ void __launch_bounds__(256, 2) persist_kernel(
        const float* __restrict__ enc, const float* __restrict__ y,
        const float* __restrict__ vd_w, const float* __restrict__ wt_w,
        const float* __restrict__ wt_b, const float* __restrict__ Wih,
        const float* __restrict__ Wd_b, const float* __restrict__ bih,
        const float* __restrict__ bhh) {
    __shared__ float s_x1[2][Mn], s_v[Mn], s_ls[2][Tn], s_red[2][4], s_yt[2];
    s_v[threadIdx.x] = vd_w[threadIdx.x];    // loop-invariant
    __syncthreads();

    const int pc   = blockIdx.x;
    const int half = threadIdx.x >> 7;       // 0 or 1
    const int htid = threadIdx.x & 127;

    // register-cache v for this lane's 4 pairs (same mapping as px)
    float pv[8];
    {
        const int l = htid & 31;
        #pragma unroll
        for (int j = 0; j < 4; j++) {
            int p = l + 32 * j;
            float2 vv = *(const float2*)&s_v[2 * p];
            pv[2 * j]     = vv.x;
            pv[2 * j + 1] = vv.y;
        }
    }

    int ep = 0;
    for (int t = 0; t < Tn; t++) {
        if (pc < 64) {
            // x1 split-K2: task id = pc
            const int kh = pc & 1, c = (pc >> 1) & 3, r = pc >> 3;
            mma_tile64<true, false>(g_hs_hi, g_hs_lo, 512, g_Wd_hi, g_Wd_lo, 512,
                             kh ? g_x1p1 : g_x1p0, nullptr, Mn, r * 64, c * 64,
                             kh * 256, 256, kh ? nullptr : Wd_b, nullptr);
        } else {
            // gh split-K2: first task pc-64; CTAs 64..87 take task 232+(pc-64)
            int g = pc - 64;
            {
                const int kh = g & 1, c = (g >> 1) & 15, r = g >> 5;
                mma_tile64<true, false>(g_hs_hi, g_hs_lo, 512, g_Whh_hi, g_Whh_lo, 256,
                                 kh ? g_ghp1 : g_ghp0, nullptr, G4n, r * 64, c * 64,
                                 kh * 128, 128,
                                 kh ? nullptr : bih, kh ? nullptr : bhh);
            }
            if (pc < 88) {
                g = 232 + (pc - 64);
                const int kh = g & 1, c = (g >> 1) & 15, r = g >> 5;
                mma_tile64<true, false>(g_hs_hi, g_hs_lo, 512, g_Whh_hi, g_Whh_lo, 256,
                                 kh ? g_ghp1 : g_ghp0, nullptr, G4n, r * 64, c * 64,
                                 kh * 128, 128,
                                 kh ? nullptr : bih, kh ? nullptr : bhh);
            }
        }
        ep++; grid_barrier(ep * NC);

        if (pc < 256)
            attn_half(2 * pc + half, t, htid, enc, y, wt_w, wt_b, Wih,
                      s_x1[half], pv, s_ls[half], s_red[half], &s_yt[half]);
        ep++; grid_barrier(ep * NC);
    }
}

// ---------------- y_Tp1 head (warp per batch row) ---------------------------
__global__ void __launch_bounds__(256) head1_kernel(float* __restrict__ out) {
    int w = threadIdx.x >> 5, l = threadIdx.x & 31;
    int b = blockIdx.x * 8 + w;
    float sum = 0.0f;
    #pragma unroll
    for (int j = l; j < Pn; j += 32)
        sum += g_hs[b * 512 + j] * g_u[j] + g_ct[b * Mn + j] * g_u[Pn + j];
    #pragma unroll
    for (int o = 16; o > 0; o >>= 1) sum += __shfl_xor_sync(0xffffffffu, sum, o);
    if (l == 0) out[b] = sum + g_u[2 * Pn];
}

// ---------------- extra step e (0 or 1): y_til, LSTM, head ------------------
__global__ void __launch_bounds__(256) extra_step_kernel(
        const float* __restrict__ tar, const int* __restrict__ trainp,
        const float* __restrict__ wt_w, const float* __restrict__ wt_b,
        const float* __restrict__ Wih, float* __restrict__ out, int e) {
    const int b = blockIdx.x, tid = threadIdx.x;
    __shared__ float red8[8];
    __shared__ float s_ytil;

    const float ct = g_ct[b * Mn + tid];
    float dct = block_reduce_256(ct * wt_w[tid], red8);
    if (tid == 0) {
        int train = (trainp[0] != 0);
        float inp = train ? tar[b * 2 + e] : out[e * Bn + b];
        s_ytil = dct + inp * wt_w[Mn] + wt_b[0];
    }
    __syncthreads();
    const float ytil = s_ytil;

    const float* gh0 = &g_ghp0[(size_t)b * G4n];
    const float* gh1 = &g_ghp1[(size_t)b * G4n];
    float ig = gh0[tid]        + gh1[tid]        + ytil * Wih[tid];
    float fg = gh0[tid + Pn]   + gh1[tid + Pn]   + ytil * Wih[tid + Pn];
    float gg = gh0[tid + 2*Pn] + gh1[tid + 2*Pn] + ytil * Wih[tid + 2*Pn];
    float og = gh0[tid + 3*Pn] + gh1[tid + 3*Pn] + ytil * Wih[tid + 3*Pn];
    float so = g_hs[b * 512 + 256 + tid];
    float cn = sigm(fg) * so + sigm(ig) * tanh_acc(gg);
    float hn = sigm(og) * tanh_acc(cn);
    g_hs[b * 512 + 256 + tid] = cn;
    g_hs[b * 512 + tid]       = hn;
    split_store(hn, &g_hs_hi[b * 512 + tid],       &g_hs_lo[b * 512 + tid]);
    split_store(cn, &g_hs_hi[b * 512 + 256 + tid], &g_hs_lo[b * 512 + 256 + tid]);

    float tot = block_reduce_256(hn * g_u[tid] + ct * g_u[Pn + tid], red8);
    if (tid == 0) out[(e + 1) * Bn + b] = tot + g_u[2 * Pn];
}

// ---------------- launcher --------------------------------------------------
extern "C" void kernel_launch(void* const* d_in, const int* in_sizes, int n_in,
                              void* d_out, int out_size) {
    const float* enc   = (const float*)d_in[0];
    const float* y     = (const float*)d_in[1];
    const float* tar   = (const float*)d_in[2];
    const int*   train = (const int*)  d_in[3];
    const float* Wd_w  = (const float*)d_in[4];
    const float* Wd_b  = (const float*)d_in[5];
    const float* Ud_w  = (const float*)d_in[6];
    const float* vd_w  = (const float*)d_in[7];
    const float* wt_w  = (const float*)d_in[8];
    const float* wt_b  = (const float*)d_in[9];
    const float* Wy_w  = (const float*)d_in[10];
    const float* Wy_b  = (const float*)d_in[11];
    const float* vy_w  = (const float*)d_in[12];
    const float* vy_b  = (const float*)d_in[13];
    const float* Wih   = (const float*)d_in[14];
    const float* Whh   = (const float*)d_in[15];
    const float* bih   = (const float*)d_in[16];
    const float* bhh   = (const float*)d_in[17];
    float* out = (float*)d_out;

    conv_enc_kernel<<<8192, 256>>>(enc);                 // launch 1
    conv_weights_kernel<<<1024, 256>>>(Wd_w, Whh, Ud_w); // launch 2 (+init)
    y1_mma_kernel<<<dim3(512, 4), 256>>>();              // launch 3

    persist_kernel<<<NC, 256>>>(enc, y, vd_w, wt_w, wt_b, Wih, Wd_b, bih, bhh); // launch 4

    compute_u_kernel<<<64, 256>>>(vy_w, Wy_w, Wy_b, vy_b);
    head1_kernel<<<Bn / 8, 256>>>(out);

    for (int e = 0; e < 2; e++) {
        step_gemm_gh<<<dim3(8, 32), 256>>>(bih, bhh);
        extra_step_kernel<<<Bn, 256>>>(tar, train, wt_w, wt_b, Wih, out, e);
    }
}